// round 14
// baseline (speedup 1.0000x reference)
#include <cuda_runtime.h>
#include <cuda_fp16.h>
#include <math.h>
#include <stdint.h>

#define TOK   4096
#define FDIM  1024
#define NHEAD 16
#define DHEAD 64
#define MLPD  4096
#define NSEQ  2048

// ---------------------------------------------------------------------------
// Scratch (device globals: allocation-free per harness rules)
// ---------------------------------------------------------------------------
__device__ float  g_out [TOK * FDIM];   // residual-1 output (fp32)
__device__ __half g_hh  [TOK * FDIM];   // LN1 output (fp16)
__device__ __half g_qh  [TOK * FDIM];   // [b][h][n][dh] fp16
__device__ __half g_kh  [TOK * FDIM];
__device__ __half g_vh  [TOK * FDIM];
__device__ __half g_attnh[TOK * FDIM];  // attention out (fp16)
__device__ __half g_h2h [TOK * FDIM];   // LN2 output (fp16)
__device__ __half g_m1h [TOK * MLPD];   // MLP hidden (fp16)
// fp16 weight copies (converted once per launch)
__device__ __half g_wq[FDIM * FDIM];    // [K][N]
__device__ __half g_wk[FDIM * FDIM];
__device__ __half g_wv[FDIM * FDIM];
__device__ __half g_wo[FDIM * FDIM];
__device__ __half g_w1[FDIM * MLPD];
__device__ __half g_w2[MLPD * FDIM];

__device__ __forceinline__ float gelu_exact(float x) {
    return 0.5f * x * (1.0f + erff(x * 0.70710678118654752f));
}

__device__ __forceinline__ uint32_t pack_h2(float lo, float hi) {
    __half2 h = __floats2half2_rn(lo, hi);
    return *reinterpret_cast<uint32_t*>(&h);
}

__device__ __forceinline__ void mma_f16(float c[4],
                                        uint32_t a0, uint32_t a1, uint32_t a2, uint32_t a3,
                                        uint32_t b0, uint32_t b1) {
    asm volatile(
        "mma.sync.aligned.m16n8k16.row.col.f32.f16.f16.f32 "
        "{%0,%1,%2,%3}, {%4,%5,%6,%7}, {%8,%9}, {%0,%1,%2,%3};"
        : "+f"(c[0]), "+f"(c[1]), "+f"(c[2]), "+f"(c[3])
        : "r"(a0), "r"(a1), "r"(a2), "r"(a3), "r"(b0), "r"(b1));
}

__device__ __forceinline__ void ldsm_x4(uint32_t& r0, uint32_t& r1,
                                        uint32_t& r2, uint32_t& r3,
                                        const __half* p) {
    uint32_t a = (uint32_t)__cvta_generic_to_shared(p);
    asm volatile("ldmatrix.sync.aligned.m8n8.x4.shared.b16 {%0,%1,%2,%3}, [%4];"
                 : "=r"(r0), "=r"(r1), "=r"(r2), "=r"(r3) : "r"(a));
}

__device__ __forceinline__ void ldsm_x4_t(uint32_t& r0, uint32_t& r1,
                                          uint32_t& r2, uint32_t& r3,
                                          const __half* p) {
    uint32_t a = (uint32_t)__cvta_generic_to_shared(p);
    asm volatile("ldmatrix.sync.aligned.m8n8.x4.trans.shared.b16 {%0,%1,%2,%3}, [%4];"
                 : "=r"(r0), "=r"(r1), "=r"(r2), "=r"(r3) : "r"(a));
}

__device__ __forceinline__ void cp16(__half* smem, const __half* gmem) {
    uint32_t s = (uint32_t)__cvta_generic_to_shared(smem);
    asm volatile("cp.async.cg.shared.global [%0], [%1], 16;" :: "r"(s), "l"(gmem));
}
#define CP_COMMIT() asm volatile("cp.async.commit_group;")
#define CP_WAIT2()  asm volatile("cp.async.wait_group 2;")

// ---------------------------------------------------------------------------
// fp32 -> fp16 weight conversion
// ---------------------------------------------------------------------------
__global__ void __launch_bounds__(256) f2h4_kernel(
    const float* __restrict__ w0, const float* __restrict__ w1,
    const float* __restrict__ w2, const float* __restrict__ w3,
    __half* __restrict__ o0, __half* __restrict__ o1,
    __half* __restrict__ o2, __half* __restrict__ o3) {
    const float* in = (blockIdx.y == 0) ? w0 : (blockIdx.y == 1) ? w1
                    : (blockIdx.y == 2) ? w2 : w3;
    __half* out = (blockIdx.y == 0) ? o0 : (blockIdx.y == 1) ? o1
                : (blockIdx.y == 2) ? o2 : o3;
    int i = (blockIdx.x * 256 + threadIdx.x) * 4;
    float4 v = *reinterpret_cast<const float4*>(in + i);
    uint2 u = make_uint2(pack_h2(v.x, v.y), pack_h2(v.z, v.w));
    *reinterpret_cast<uint2*>(out + i) = u;
}

__global__ void __launch_bounds__(256) f2h_kernel(const float* __restrict__ in,
                                                  __half* __restrict__ out, int n) {
    int i = (blockIdx.x * 256 + threadIdx.x) * 4;
    if (i < n) {
        float4 v = *reinterpret_cast<const float4*>(in + i);
        uint2 u = make_uint2(pack_h2(v.x, v.y), pack_h2(v.z, v.w));
        *reinterpret_cast<uint2*>(out + i) = u;
    }
}

// ---------------------------------------------------------------------------
// LayerNorm: one block per row; fp16 output.
// ---------------------------------------------------------------------------
__global__ void __launch_bounds__(256) ln_kernel(const float* __restrict__ x,
                                                 const float* __restrict__ g,
                                                 const float* __restrict__ b,
                                                 __half* __restrict__ out) {
    int row = blockIdx.x;
    const float4* xr = reinterpret_cast<const float4*>(x + (size_t)row * FDIM);
    float4 v = xr[threadIdx.x];

    float s  = v.x + v.y + v.z + v.w;
    float s2 = v.x * v.x + v.y * v.y + v.z * v.z + v.w * v.w;

    #pragma unroll
    for (int o = 16; o > 0; o >>= 1) {
        s  += __shfl_xor_sync(0xffffffffu, s,  o);
        s2 += __shfl_xor_sync(0xffffffffu, s2, o);
    }
    __shared__ float ss[8], ss2[8];
    int w = threadIdx.x >> 5, lane = threadIdx.x & 31;
    if (lane == 0) { ss[w] = s; ss2[w] = s2; }
    __syncthreads();
    s = 0.f; s2 = 0.f;
    #pragma unroll
    for (int i = 0; i < 8; i++) { s += ss[i]; s2 += ss2[i]; }

    float mu  = s * (1.0f / FDIM);
    float var = s2 * (1.0f / FDIM) - mu * mu;
    float r   = rsqrtf(var + 1e-5f);

    float4 gg = reinterpret_cast<const float4*>(g)[threadIdx.x];
    float4 bb = reinterpret_cast<const float4*>(b)[threadIdx.x];
    float o0 = (v.x - mu) * r * gg.x + bb.x;
    float o1 = (v.y - mu) * r * gg.y + bb.y;
    float o2 = (v.z - mu) * r * gg.z + bb.z;
    float o3 = (v.w - mu) * r * gg.w + bb.w;
    uint2 u = make_uint2(pack_h2(o0, o1), pack_h2(o2, o3));
    *reinterpret_cast<uint2*>(out + (size_t)row * FDIM + threadIdx.x * 4) = u;
}

// ---------------------------------------------------------------------------
// FP16 GEMM (fp32 accumulate), cp.async 4-stage pipeline + ldmatrix.
// C[M,N] = A[M,K] @ B[K,N] + bias.  A,B fp16; epilogue fp32 or fp16 out.
// BM=BN=128, BK=32, 256 threads = 8 warps (2m x 4n), warp tile 64x32.
// One __syncthreads per slab; wait_group 2 keeps two tile-loads in flight.
// ---------------------------------------------------------------------------
#define ASTR 40
#define BSTR 136
#define A_TILE_H (128 * ASTR)
#define B_TILE_H (32 * BSTR)
#define STAGE_H  (A_TILE_H + B_TILE_H)
#define GEMM_SMEM (4 * STAGE_H * 2)     // 75776 bytes

template <bool GELU, bool RES, bool QKV, bool OUTH>
__device__ __forceinline__ void gemm_body(
    const __half* __restrict__ A, const __half* __restrict__ B,
    const float* __restrict__ bias, const float* __restrict__ res,
    void* __restrict__ Cv, int N, int K,
    __half* sm, int bx, int by)
{
    const int tid    = threadIdx.x;
    const int warp   = tid >> 5;
    const int lane   = tid & 31;
    const int g      = lane >> 2;
    const int tig    = lane & 3;
    const int lane15 = lane & 15;
    const int lhalf  = lane >> 4;
    const int warp_m = (warp & 1) * 64;
    const int warp_n = (warp >> 1) * 32;

    const __half* Abase = A + (size_t)by * 128 * K;
    const __half* Bbase = B + bx * 128;

    const int a_r0 = tid >> 2, a_c = tid & 3;     // A: 2 x (64 rows apart)
    const int b_c = tid & 15;                     // B: 2 x (16 k-rows apart)

    float acc[4][4][4];
    #pragma unroll
    for (int mt = 0; mt < 4; mt++)
        #pragma unroll
        for (int nt = 0; nt < 4; nt++)
            #pragma unroll
            for (int r = 0; r < 4; r++) acc[mt][nt][r] = 0.f;

    const int nk = K >> 5;

    auto load_stage = [&](int kt, int s) {
        __half* Asm = sm + s * STAGE_H;
        __half* Bsm = Asm + A_TILE_H;
        const __half* Ag = Abase + kt * 32;
        const __half* Bg = Bbase + (size_t)kt * 32 * N;
        #pragma unroll
        for (int i = 0; i < 2; i++) {
            int r = a_r0 + i * 64;
            cp16(Asm + r * ASTR + a_c * 8, Ag + (size_t)r * K + a_c * 8);
        }
        #pragma unroll
        for (int i = 0; i < 2; i++) {
            int idx = tid + i * 256;
            int r = idx >> 4;
            cp16(Bsm + r * BSTR + b_c * 8, Bg + (size_t)r * N + b_c * 8);
        }
    };

    load_stage(0, 0); CP_COMMIT();
    load_stage(1, 1); CP_COMMIT();
    load_stage(2, 2); CP_COMMIT();

    for (int kt = 0; kt < nk; kt++) {
        CP_WAIT2();          // group kt complete (kt+1, kt+2 may be in flight)
        __syncthreads();     // all warps: data visible AND prior slab's reads done

        // refill the buffer consumed in slab kt-1 (safe: everyone passed sync)
        if (kt + 3 < nk) load_stage(kt + 3, (kt + 3) & 3);
        CP_COMMIT();

        const __half* Ac = sm + (kt & 3) * STAGE_H;
        const __half* Bc = Ac + A_TILE_H;

        #pragma unroll
        for (int ks = 0; ks < 2; ks++) {
            uint32_t af[4][4], bf[4][2];
            #pragma unroll
            for (int mt = 0; mt < 4; mt++)
                ldsm_x4(af[mt][0], af[mt][1], af[mt][2], af[mt][3],
                        Ac + (warp_m + mt * 16 + lane15) * ASTR + ks * 16 + lhalf * 8);
            #pragma unroll
            for (int ntp = 0; ntp < 2; ntp++)
                ldsm_x4_t(bf[2 * ntp][0], bf[2 * ntp][1], bf[2 * ntp + 1][0], bf[2 * ntp + 1][1],
                          Bc + (ks * 16 + lane15) * BSTR + warp_n + ntp * 16 + lhalf * 8);
            #pragma unroll
            for (int mt = 0; mt < 4; mt++)
                #pragma unroll
                for (int nt = 0; nt < 4; nt++)
                    mma_f16(acc[mt][nt], af[mt][0], af[mt][1], af[mt][2], af[mt][3],
                            bf[nt][0], bf[nt][1]);
        }
        // no bottom sync: next iteration's top sync provides the guarantee
    }

    // --- Epilogue ---
    const int rowbase = by * 128 + warp_m;
    const int colbase = bx * 128 + warp_n;

    #pragma unroll
    for (int mt = 0; mt < 4; mt++) {
        #pragma unroll
        for (int nt = 0; nt < 4; nt++) {
            int c = colbase + nt * 8 + tig * 2;
            float bx_ = bias[c], by_ = bias[c + 1];
            #pragma unroll
            for (int half = 0; half < 2; half++) {
                int r = rowbase + mt * 16 + g + half * 8;
                float v0 = acc[mt][nt][half * 2 + 0] + bx_;
                float v1 = acc[mt][nt][half * 2 + 1] + by_;
                if (GELU) { v0 = gelu_exact(v0); v1 = gelu_exact(v1); }
                if (RES) {
                    float2 rr = *reinterpret_cast<const float2*>(res + (size_t)r * N + c);
                    v0 += rr.x; v1 += rr.y;
                }
                size_t off;
                if (QKV) {
                    int b = r >> 11;
                    int n = r & 2047;
                    int h = c >> 6;
                    int d = c & 63;
                    off = ((size_t)((b * NHEAD + h) * NSEQ + n)) * DHEAD + d;
                } else {
                    off = (size_t)r * N + c;
                }
                if (OUTH) {
                    __half2 hv = __floats2half2_rn(v0, v1);
                    *reinterpret_cast<__half2*>((__half*)Cv + off) = hv;
                } else {
                    *reinterpret_cast<float2*>((float*)Cv + off) = make_float2(v0, v1);
                }
            }
        }
    }
}

template <bool GELU, bool RES, bool QKV, bool OUTH>
__global__ void __launch_bounds__(256) hgemm(
    const __half* __restrict__ A, const __half* __restrict__ B,
    const float* __restrict__ bias, const float* __restrict__ res,
    void* __restrict__ C, int N, int K)
{
    extern __shared__ __half sm[];
    gemm_body<GELU, RES, QKV, OUTH>(A, B, bias, res, C, N, K, sm, blockIdx.x, blockIdx.y);
}

// Fused Q/K/V projection: gridDim.z selects weight/bias/output.
__global__ void __launch_bounds__(256) qkv_gemm(
    const __half* __restrict__ A,
    const __half* __restrict__ W0, const __half* __restrict__ W1, const __half* __restrict__ W2,
    const float* __restrict__ b0, const float* __restrict__ b1, const float* __restrict__ b2,
    __half* __restrict__ C0, __half* __restrict__ C1, __half* __restrict__ C2)
{
    extern __shared__ __half sm[];
    const __half* B    = (blockIdx.z == 0) ? W0 : (blockIdx.z == 1) ? W1 : W2;
    const float* bias  = (blockIdx.z == 0) ? b0 : (blockIdx.z == 1) ? b1 : b2;
    __half*      C     = (blockIdx.z == 0) ? C0 : (blockIdx.z == 1) ? C1 : C2;
    gemm_body<false, false, true, true>(A, B, bias, nullptr, C, FDIM, FDIM,
                                        sm, blockIdx.x, blockIdx.y);
}

// ---------------------------------------------------------------------------
// FP16 tensor-core flash attention (unchanged from R12 passing version).
// ---------------------------------------------------------------------------
#define QSTR 72

__global__ void __launch_bounds__(128) attn_h(
    const __half* __restrict__ q, const __half* __restrict__ k,
    const __half* __restrict__ v, const float* __restrict__ slim,
    __half* __restrict__ out)
{
    __shared__ __half Ks[64 * QSTR];
    __shared__ __half Vs[64 * QSTR];

    const int bh = blockIdx.x;
    const int b  = bh >> 4;
    const int h  = bh & 15;
    const int qbase = blockIdx.y * 64;

    const int tid    = threadIdx.x;
    const int w      = tid >> 5;
    const int lane   = tid & 31;
    const int g      = lane >> 2;
    const int tig    = lane & 3;
    const int lane15 = lane & 15;
    const int lhalf  = lane >> 4;

    const uint4* Qg = reinterpret_cast<const uint4*>(
        q + ((size_t)bh * NSEQ + qbase) * DHEAD);
    #pragma unroll
    for (int i = 0; i < 4; i++) {
        int idx = tid + i * 128;
        int r = idx >> 3, c = idx & 7;
        *reinterpret_cast<uint4*>(Ks + r * QSTR + c * 8) = Qg[r * 8 + c];
    }
    __syncthreads();

    uint32_t qa[4][4];
    #pragma unroll
    for (int ks = 0; ks < 4; ks++)
        ldsm_x4(qa[ks][0], qa[ks][1], qa[ks][2], qa[ks][3],
                Ks + (w * 16 + lane15) * QSTR + ks * 16 + lhalf * 8);

    float oacc[8][4];
    #pragma unroll
    for (int nt = 0; nt < 8; nt++)
        #pragma unroll
        for (int r = 0; r < 4; r++) oacc[nt][r] = 0.f;
    float m0 = -1e30f, m1 = -1e30f, l0 = 0.f, l1 = 0.f;

    const uint4* Kg = reinterpret_cast<const uint4*>(k + (size_t)bh * NSEQ * DHEAD);
    const uint4* Vg = reinterpret_cast<const uint4*>(v + (size_t)bh * NSEQ * DHEAD);

    for (int kt = 0; kt < NSEQ / 64; kt++) {
        __syncthreads();
        #pragma unroll
        for (int i = 0; i < 4; i++) {
            int idx = tid + i * 128;
            int r = idx >> 3, c = idx & 7;
            *reinterpret_cast<uint4*>(Ks + r * QSTR + c * 8) = Kg[(kt * 64 + r) * 8 + c];
            *reinterpret_cast<uint4*>(Vs + r * QSTR + c * 8) = Vg[(kt * 64 + r) * 8 + c];
        }
        __syncthreads();

        float sacc[8][4];
        #pragma unroll
        for (int nt = 0; nt < 8; nt++)
            #pragma unroll
            for (int r = 0; r < 4; r++) sacc[nt][r] = 0.f;

        #pragma unroll
        for (int ks = 0; ks < 4; ks++) {
            uint32_t kb[8][2];
            #pragma unroll
            for (int ntp = 0; ntp < 4; ntp++) {
                int row = ntp * 16 + ((lane & 16) >> 1) + (lane & 7);
                int kof = ks * 16 + (lane & 8);
                ldsm_x4(kb[2 * ntp][0], kb[2 * ntp][1], kb[2 * ntp + 1][0], kb[2 * ntp + 1][1],
                        Ks + row * QSTR + kof);
            }
            #pragma unroll
            for (int nt = 0; nt < 8; nt++)
                mma_f16(sacc[nt], qa[ks][0], qa[ks][1], qa[ks][2], qa[ks][3],
                        kb[nt][0], kb[nt][1]);
        }

        float tm0 = -1e30f, tm1 = -1e30f;
        #pragma unroll
        for (int nt = 0; nt < 8; nt++) {
            tm0 = fmaxf(tm0, fmaxf(sacc[nt][0], sacc[nt][1]));
            tm1 = fmaxf(tm1, fmaxf(sacc[nt][2], sacc[nt][3]));
        }
        tm0 = fmaxf(tm0, __shfl_xor_sync(0xffffffffu, tm0, 1));
        tm0 = fmaxf(tm0, __shfl_xor_sync(0xffffffffu, tm0, 2));
        tm1 = fmaxf(tm1, __shfl_xor_sync(0xffffffffu, tm1, 1));
        tm1 = fmaxf(tm1, __shfl_xor_sync(0xffffffffu, tm1, 2));

        float nm0 = fmaxf(m0, tm0), nm1 = fmaxf(m1, tm1);
        float f0 = __expf((m0 - nm0) * 0.125f), f1 = __expf((m1 - nm1) * 0.125f);
        m0 = nm0; m1 = nm1;

        uint32_t pch[8][2];
        float ps0 = 0.f, ps1 = 0.f;
        #pragma unroll
        for (int nt = 0; nt < 8; nt++) {
            float p0 = __expf((sacc[nt][0] - m0) * 0.125f);
            float p1 = __expf((sacc[nt][1] - m0) * 0.125f);
            float p2 = __expf((sacc[nt][2] - m1) * 0.125f);
            float p3 = __expf((sacc[nt][3] - m1) * 0.125f);
            ps0 += p0 + p1; ps1 += p2 + p3;
            pch[nt][0] = pack_h2(p0, p1);
            pch[nt][1] = pack_h2(p2, p3);
        }
        ps0 += __shfl_xor_sync(0xffffffffu, ps0, 1);
        ps0 += __shfl_xor_sync(0xffffffffu, ps0, 2);
        ps1 += __shfl_xor_sync(0xffffffffu, ps1, 1);
        ps1 += __shfl_xor_sync(0xffffffffu, ps1, 2);
        l0 = l0 * f0 + ps0;
        l1 = l1 * f1 + ps1;

        #pragma unroll
        for (int nt = 0; nt < 8; nt++) {
            oacc[nt][0] *= f0; oacc[nt][1] *= f0;
            oacc[nt][2] *= f1; oacc[nt][3] *= f1;
        }

        #pragma unroll
        for (int kb2 = 0; kb2 < 4; kb2++) {
            uint32_t pa0 = pch[2 * kb2][0];
            uint32_t pa1 = pch[2 * kb2][1];
            uint32_t pa2 = pch[2 * kb2 + 1][0];
            uint32_t pa3 = pch[2 * kb2 + 1][1];
            uint32_t vb[8][2];
            #pragma unroll
            for (int ntp = 0; ntp < 4; ntp++)
                ldsm_x4_t(vb[2 * ntp][0], vb[2 * ntp][1], vb[2 * ntp + 1][0], vb[2 * ntp + 1][1],
                          Vs + (kb2 * 16 + lane15) * QSTR + ntp * 16 + lhalf * 8);
            #pragma unroll
            for (int nt = 0; nt < 8; nt++)
                mma_f16(oacc[nt], pa0, pa1, pa2, pa3, vb[nt][0], vb[nt][1]);
        }
    }

    float sl = slim[h];
    float inv0 = sl / (1.0f + l0);
    float inv1 = sl / (1.0f + l1);
    int q0 = qbase + w * 16 + g;
    __half* ob0 = out + ((size_t)(b * NSEQ + q0))     * FDIM + h * DHEAD;
    __half* ob1 = out + ((size_t)(b * NSEQ + q0 + 8)) * FDIM + h * DHEAD;
    #pragma unroll
    for (int nt = 0; nt < 8; nt++) {
        int d = nt * 8 + tig * 2;
        *reinterpret_cast<__half2*>(ob0 + d) =
            __floats2half2_rn(oacc[nt][0] * inv0, oacc[nt][1] * inv0);
        *reinterpret_cast<__half2*>(ob1 + d) =
            __floats2half2_rn(oacc[nt][2] * inv1, oacc[nt][3] * inv1);
    }
}

// ---------------------------------------------------------------------------
// Launch
// ---------------------------------------------------------------------------
extern "C" void kernel_launch(void* const* d_in, const int* in_sizes, int n_in,
                              void* d_out, int out_size)
{
    const float* x    = (const float*)d_in[0];
    const float* ln1g = (const float*)d_in[1];
    const float* ln1b = (const float*)d_in[2];
    const float* Wq   = (const float*)d_in[3];
    const float* bq   = (const float*)d_in[4];
    const float* Wk   = (const float*)d_in[5];
    const float* bk   = (const float*)d_in[6];
    const float* Wv   = (const float*)d_in[7];
    const float* bv   = (const float*)d_in[8];
    const float* Wo   = (const float*)d_in[9];
    const float* bo   = (const float*)d_in[10];
    const float* slim = (const float*)d_in[11];
    const float* ln2g = (const float*)d_in[12];
    const float* ln2b = (const float*)d_in[13];
    const float* W1   = (const float*)d_in[14];
    const float* b1   = (const float*)d_in[15];
    const float* W2   = (const float*)d_in[16];
    const float* b2   = (const float*)d_in[17];
    float* out = (float*)d_out;

    float* pout;
    __half *phh, *pqh, *pkh, *pvh, *pah, *ph2, *pm1;
    __half *pwq, *pwk, *pwv, *pwo, *pw1, *pw2;
    cudaGetSymbolAddress((void**)&pout, g_out);
    cudaGetSymbolAddress((void**)&phh,  g_hh);
    cudaGetSymbolAddress((void**)&pqh,  g_qh);
    cudaGetSymbolAddress((void**)&pkh,  g_kh);
    cudaGetSymbolAddress((void**)&pvh,  g_vh);
    cudaGetSymbolAddress((void**)&pah,  g_attnh);
    cudaGetSymbolAddress((void**)&ph2,  g_h2h);
    cudaGetSymbolAddress((void**)&pm1,  g_m1h);
    cudaGetSymbolAddress((void**)&pwq,  g_wq);
    cudaGetSymbolAddress((void**)&pwk,  g_wk);
    cudaGetSymbolAddress((void**)&pwv,  g_wv);
    cudaGetSymbolAddress((void**)&pwo,  g_wo);
    cudaGetSymbolAddress((void**)&pw1,  g_w1);
    cudaGetSymbolAddress((void**)&pw2,  g_w2);

    cudaFuncSetAttribute(qkv_gemm, cudaFuncAttributeMaxDynamicSharedMemorySize, GEMM_SMEM);
    cudaFuncSetAttribute(hgemm<false, true, false, false>,
                         cudaFuncAttributeMaxDynamicSharedMemorySize, GEMM_SMEM);
    cudaFuncSetAttribute(hgemm<true, false, false, true>,
                         cudaFuncAttributeMaxDynamicSharedMemorySize, GEMM_SMEM);
    cudaFuncSetAttribute(hgemm<true, true, false, false>,
                         cudaFuncAttributeMaxDynamicSharedMemorySize, GEMM_SMEM);

    // 0. weight conversions
    f2h4_kernel<<<dim3(FDIM * FDIM / 1024, 4), 256>>>(Wq, Wk, Wv, Wo, pwq, pwk, pwv, pwo);
    f2h_kernel<<<FDIM * MLPD / 1024, 256>>>(W1, pw1, FDIM * MLPD);
    f2h_kernel<<<MLPD * FDIM / 1024, 256>>>(W2, pw2, MLPD * FDIM);

    dim3 gF(FDIM / 128, TOK / 128);
    dim3 gQ(FDIM / 128, TOK / 128, 3);
    dim3 gM(MLPD / 128, TOK / 128);

    // 1. LN1 -> fp16
    ln_kernel<<<TOK, 256>>>(x, ln1g, ln1b, phh);

    // 2. fused QKV projections -> fp16 [b,h,n,d]
    qkv_gemm<<<gQ, 256, GEMM_SMEM>>>(phh, pwq, pwk, pwv, bq, bk, bv, pqh, pkh, pvh);

    // 3. fp16 flash attention
    attn_h<<<dim3(2 * NHEAD, NSEQ / 64), 128>>>(pqh, pkh, pvh, slim, pah);

    // 4. output projection + residual 1 -> fp32
    hgemm<false, true, false, false><<<gF, 256, GEMM_SMEM>>>(pah, pwo, bo, x, pout, FDIM, FDIM);

    // 5. LN2 -> fp16
    ln_kernel<<<TOK, 256>>>(pout, ln2g, ln2b, ph2);

    // 6. MLP up + GELU -> fp16
    hgemm<true, false, false, true><<<gM, 256, GEMM_SMEM>>>(ph2, pw1, b1, nullptr, pm1, MLPD, FDIM);

    // 7. MLP down + GELU + residual 2 -> fp32 final
    hgemm<true, true, false, false><<<gF, 256, GEMM_SMEM>>>(pm1, pw2, b2, pout, out, FDIM, MLPD);
}

// round 15
// speedup vs baseline: 1.0344x; 1.0344x over previous
#include <cuda_runtime.h>
#include <cuda_fp16.h>
#include <math.h>
#include <stdint.h>

#define TOK   4096
#define FDIM  1024
#define NHEAD 16
#define DHEAD 64
#define MLPD  4096
#define NSEQ  2048

// ---------------------------------------------------------------------------
// Scratch (device globals: allocation-free per harness rules)
// ---------------------------------------------------------------------------
__device__ float  g_out [TOK * FDIM];   // residual-1 output (fp32)
__device__ __half g_hh  [TOK * FDIM];   // LN1 output (fp16)
__device__ __half g_qh  [TOK * FDIM];   // [b][h][n][dh] fp16
__device__ __half g_kh  [TOK * FDIM];
__device__ __half g_vh  [TOK * FDIM];
__device__ __half g_attnh[TOK * FDIM];  // attention out (fp16)
__device__ __half g_h2h [TOK * FDIM];   // LN2 output (fp16)
__device__ __half g_m1h [TOK * MLPD];   // MLP hidden (fp16)
// fp16 weight copies (converted once per launch)
__device__ __half g_wq[FDIM * FDIM];    // [K][N]
__device__ __half g_wk[FDIM * FDIM];
__device__ __half g_wv[FDIM * FDIM];
__device__ __half g_wo[FDIM * FDIM];
__device__ __half g_w1[FDIM * MLPD];
__device__ __half g_w2[MLPD * FDIM];

__device__ __forceinline__ float gelu_exact(float x) {
    return 0.5f * x * (1.0f + erff(x * 0.70710678118654752f));
}

__device__ __forceinline__ uint32_t pack_h2(float lo, float hi) {
    __half2 h = __floats2half2_rn(lo, hi);
    return *reinterpret_cast<uint32_t*>(&h);
}

__device__ __forceinline__ void mma_f16(float c[4],
                                        uint32_t a0, uint32_t a1, uint32_t a2, uint32_t a3,
                                        uint32_t b0, uint32_t b1) {
    asm volatile(
        "mma.sync.aligned.m16n8k16.row.col.f32.f16.f16.f32 "
        "{%0,%1,%2,%3}, {%4,%5,%6,%7}, {%8,%9}, {%0,%1,%2,%3};"
        : "+f"(c[0]), "+f"(c[1]), "+f"(c[2]), "+f"(c[3])
        : "r"(a0), "r"(a1), "r"(a2), "r"(a3), "r"(b0), "r"(b1));
}

__device__ __forceinline__ void ldsm_x4(uint32_t& r0, uint32_t& r1,
                                        uint32_t& r2, uint32_t& r3,
                                        const __half* p) {
    uint32_t a = (uint32_t)__cvta_generic_to_shared(p);
    asm volatile("ldmatrix.sync.aligned.m8n8.x4.shared.b16 {%0,%1,%2,%3}, [%4];"
                 : "=r"(r0), "=r"(r1), "=r"(r2), "=r"(r3) : "r"(a));
}

__device__ __forceinline__ void ldsm_x4_t(uint32_t& r0, uint32_t& r1,
                                          uint32_t& r2, uint32_t& r3,
                                          const __half* p) {
    uint32_t a = (uint32_t)__cvta_generic_to_shared(p);
    asm volatile("ldmatrix.sync.aligned.m8n8.x4.trans.shared.b16 {%0,%1,%2,%3}, [%4];"
                 : "=r"(r0), "=r"(r1), "=r"(r2), "=r"(r3) : "r"(a));
}

__device__ __forceinline__ void cp16(__half* smem, const __half* gmem) {
    uint32_t s = (uint32_t)__cvta_generic_to_shared(smem);
    asm volatile("cp.async.cg.shared.global [%0], [%1], 16;" :: "r"(s), "l"(gmem));
}
#define CP_COMMIT() asm volatile("cp.async.commit_group;")
#define CP_WAIT1()  asm volatile("cp.async.wait_group 1;")

// ---------------------------------------------------------------------------
// Fused fp32 -> fp16 weight conversion: all 6 weights, 8 elements/thread.
// blockIdx.y selects weight; oversized grids guard with n.
// ---------------------------------------------------------------------------
__global__ void __launch_bounds__(256) f2h6_kernel(
    const float* __restrict__ wq, const float* __restrict__ wk,
    const float* __restrict__ wv, const float* __restrict__ wo,
    const float* __restrict__ w1, const float* __restrict__ w2,
    __half* __restrict__ oq, __half* __restrict__ ok,
    __half* __restrict__ ov, __half* __restrict__ oo,
    __half* __restrict__ o1, __half* __restrict__ o2)
{
    const float* in; __half* out; int n;
    switch (blockIdx.y) {
        case 0: in = wq; out = oq; n = FDIM * FDIM; break;
        case 1: in = wk; out = ok; n = FDIM * FDIM; break;
        case 2: in = wv; out = ov; n = FDIM * FDIM; break;
        case 3: in = wo; out = oo; n = FDIM * FDIM; break;
        case 4: in = w1; out = o1; n = FDIM * MLPD; break;
        default: in = w2; out = o2; n = MLPD * FDIM; break;
    }
    int i = (blockIdx.x * 256 + threadIdx.x) * 8;
    if (i < n) {
        float4 v0 = *reinterpret_cast<const float4*>(in + i);
        float4 v1 = *reinterpret_cast<const float4*>(in + i + 4);
        uint4 u;
        u.x = pack_h2(v0.x, v0.y); u.y = pack_h2(v0.z, v0.w);
        u.z = pack_h2(v1.x, v1.y); u.w = pack_h2(v1.z, v1.w);
        *reinterpret_cast<uint4*>(out + i) = u;
    }
}

// ---------------------------------------------------------------------------
// LayerNorm: one block per row; fp16 output.
// ---------------------------------------------------------------------------
__global__ void __launch_bounds__(256) ln_kernel(const float* __restrict__ x,
                                                 const float* __restrict__ g,
                                                 const float* __restrict__ b,
                                                 __half* __restrict__ out) {
    int row = blockIdx.x;
    const float4* xr = reinterpret_cast<const float4*>(x + (size_t)row * FDIM);
    float4 v = xr[threadIdx.x];

    float s  = v.x + v.y + v.z + v.w;
    float s2 = v.x * v.x + v.y * v.y + v.z * v.z + v.w * v.w;

    #pragma unroll
    for (int o = 16; o > 0; o >>= 1) {
        s  += __shfl_xor_sync(0xffffffffu, s,  o);
        s2 += __shfl_xor_sync(0xffffffffu, s2, o);
    }
    __shared__ float ss[8], ss2[8];
    int w = threadIdx.x >> 5, lane = threadIdx.x & 31;
    if (lane == 0) { ss[w] = s; ss2[w] = s2; }
    __syncthreads();
    s = 0.f; s2 = 0.f;
    #pragma unroll
    for (int i = 0; i < 8; i++) { s += ss[i]; s2 += ss2[i]; }

    float mu  = s * (1.0f / FDIM);
    float var = s2 * (1.0f / FDIM) - mu * mu;
    float r   = rsqrtf(var + 1e-5f);

    float4 gg = reinterpret_cast<const float4*>(g)[threadIdx.x];
    float4 bb = reinterpret_cast<const float4*>(b)[threadIdx.x];
    float o0 = (v.x - mu) * r * gg.x + bb.x;
    float o1 = (v.y - mu) * r * gg.y + bb.y;
    float o2 = (v.z - mu) * r * gg.z + bb.z;
    float o3 = (v.w - mu) * r * gg.w + bb.w;
    uint2 u = make_uint2(pack_h2(o0, o1), pack_h2(o2, o3));
    *reinterpret_cast<uint2*>(out + (size_t)row * FDIM + threadIdx.x * 4) = u;
}

// ---------------------------------------------------------------------------
// FP16 GEMM (fp32 accumulate), cp.async 3-stage pipeline + ldmatrix.
// (Known-good R12 mainloop: wait_group 1, sync top and bottom.)
// BM=BN=128, BK=32, 256 threads = 8 warps (2m x 4n), warp tile 64x32.
// ---------------------------------------------------------------------------
#define ASTR 40
#define BSTR 136
#define A_TILE_H (128 * ASTR)
#define B_TILE_H (32 * BSTR)
#define STAGE_H  (A_TILE_H + B_TILE_H)
#define GEMM_SMEM (3 * STAGE_H * 2)     // 56832 bytes

template <bool GELU, bool RES, bool QKV, bool OUTH>
__device__ __forceinline__ void gemm_body(
    const __half* __restrict__ A, const __half* __restrict__ B,
    const float* __restrict__ bias, const float* __restrict__ res,
    void* __restrict__ Cv, int N, int K,
    __half* sm, int bx, int by)
{
    const int tid    = threadIdx.x;
    const int warp   = tid >> 5;
    const int lane   = tid & 31;
    const int g      = lane >> 2;
    const int tig    = lane & 3;
    const int lane15 = lane & 15;
    const int lhalf  = lane >> 4;
    const int warp_m = (warp & 1) * 64;
    const int warp_n = (warp >> 1) * 32;

    const __half* Abase = A + (size_t)by * 128 * K;
    const __half* Bbase = B + bx * 128;

    const int a_r0 = tid >> 2, a_c = tid & 3;
    const int b_c = tid & 15;

    float acc[4][4][4];
    #pragma unroll
    for (int mt = 0; mt < 4; mt++)
        #pragma unroll
        for (int nt = 0; nt < 4; nt++)
            #pragma unroll
            for (int r = 0; r < 4; r++) acc[mt][nt][r] = 0.f;

    const int nk = K >> 5;

    auto load_stage = [&](int kt, int s) {
        __half* Asm = sm + s * STAGE_H;
        __half* Bsm = Asm + A_TILE_H;
        const __half* Ag = Abase + kt * 32;
        const __half* Bg = Bbase + (size_t)kt * 32 * N;
        #pragma unroll
        for (int i = 0; i < 2; i++) {
            int r = a_r0 + i * 64;
            cp16(Asm + r * ASTR + a_c * 8, Ag + (size_t)r * K + a_c * 8);
        }
        #pragma unroll
        for (int i = 0; i < 2; i++) {
            int idx = tid + i * 256;
            int r = idx >> 4;
            cp16(Bsm + r * BSTR + b_c * 8, Bg + (size_t)r * N + b_c * 8);
        }
    };

    load_stage(0, 0); CP_COMMIT();
    load_stage(1, 1); CP_COMMIT();

    for (int kt = 0; kt < nk; kt++) {
        CP_WAIT1();
        __syncthreads();

        if (kt + 2 < nk) load_stage(kt + 2, (kt + 2) % 3);
        CP_COMMIT();

        const __half* Ac = sm + (kt % 3) * STAGE_H;
        const __half* Bc = Ac + A_TILE_H;

        #pragma unroll
        for (int ks = 0; ks < 2; ks++) {
            uint32_t af[4][4], bf[4][2];
            #pragma unroll
            for (int mt = 0; mt < 4; mt++)
                ldsm_x4(af[mt][0], af[mt][1], af[mt][2], af[mt][3],
                        Ac + (warp_m + mt * 16 + lane15) * ASTR + ks * 16 + lhalf * 8);
            #pragma unroll
            for (int ntp = 0; ntp < 2; ntp++)
                ldsm_x4_t(bf[2 * ntp][0], bf[2 * ntp][1], bf[2 * ntp + 1][0], bf[2 * ntp + 1][1],
                          Bc + (ks * 16 + lane15) * BSTR + warp_n + ntp * 16 + lhalf * 8);
            #pragma unroll
            for (int mt = 0; mt < 4; mt++)
                #pragma unroll
                for (int nt = 0; nt < 4; nt++)
                    mma_f16(acc[mt][nt], af[mt][0], af[mt][1], af[mt][2], af[mt][3],
                            bf[nt][0], bf[nt][1]);
        }
        __syncthreads();
    }

    // --- Epilogue ---
    const int rowbase = by * 128 + warp_m;
    const int colbase = bx * 128 + warp_n;

    #pragma unroll
    for (int mt = 0; mt < 4; mt++) {
        #pragma unroll
        for (int nt = 0; nt < 4; nt++) {
            int c = colbase + nt * 8 + tig * 2;
            float bx_ = bias[c], by_ = bias[c + 1];
            #pragma unroll
            for (int half = 0; half < 2; half++) {
                int r = rowbase + mt * 16 + g + half * 8;
                float v0 = acc[mt][nt][half * 2 + 0] + bx_;
                float v1 = acc[mt][nt][half * 2 + 1] + by_;
                if (GELU) { v0 = gelu_exact(v0); v1 = gelu_exact(v1); }
                if (RES) {
                    float2 rr = *reinterpret_cast<const float2*>(res + (size_t)r * N + c);
                    v0 += rr.x; v1 += rr.y;
                }
                size_t off;
                if (QKV) {
                    int b = r >> 11;
                    int n = r & 2047;
                    int h = c >> 6;
                    int d = c & 63;
                    off = ((size_t)((b * NHEAD + h) * NSEQ + n)) * DHEAD + d;
                } else {
                    off = (size_t)r * N + c;
                }
                if (OUTH) {
                    __half2 hv = __floats2half2_rn(v0, v1);
                    *reinterpret_cast<__half2*>((__half*)Cv + off) = hv;
                } else {
                    *reinterpret_cast<float2*>((float*)Cv + off) = make_float2(v0, v1);
                }
            }
        }
    }
}

template <bool GELU, bool RES, bool QKV, bool OUTH>
__global__ void __launch_bounds__(256) hgemm(
    const __half* __restrict__ A, const __half* __restrict__ B,
    const float* __restrict__ bias, const float* __restrict__ res,
    void* __restrict__ C, int N, int K)
{
    extern __shared__ __half sm[];
    gemm_body<GELU, RES, QKV, OUTH>(A, B, bias, res, C, N, K, sm, blockIdx.x, blockIdx.y);
}

// Fused Q/K/V projection: gridDim.z selects weight/bias/output.
__global__ void __launch_bounds__(256) qkv_gemm(
    const __half* __restrict__ A,
    const __half* __restrict__ W0, const __half* __restrict__ W1, const __half* __restrict__ W2,
    const float* __restrict__ b0, const float* __restrict__ b1, const float* __restrict__ b2,
    __half* __restrict__ C0, __half* __restrict__ C1, __half* __restrict__ C2)
{
    extern __shared__ __half sm[];
    const __half* B    = (blockIdx.z == 0) ? W0 : (blockIdx.z == 1) ? W1 : W2;
    const float* bias  = (blockIdx.z == 0) ? b0 : (blockIdx.z == 1) ? b1 : b2;
    __half*      C     = (blockIdx.z == 0) ? C0 : (blockIdx.z == 1) ? C1 : C2;
    gemm_body<false, false, true, true>(A, B, bias, nullptr, C, FDIM, FDIM,
                                        sm, blockIdx.x, blockIdx.y);
}

// ---------------------------------------------------------------------------
// FP16 flash attention, 128 q-rows per block (8 warps, 256 threads).
// Each K/V tile (64 keys) now feeds 128 q-rows -> half the smem-fill traffic.
// Per-warp math identical to the validated 4-warp version.
// ---------------------------------------------------------------------------
#define QSTR 72

__global__ void __launch_bounds__(256) attn_h(
    const __half* __restrict__ q, const __half* __restrict__ k,
    const __half* __restrict__ v, const float* __restrict__ slim,
    __half* __restrict__ out)
{
    __shared__ __half KV[128 * QSTR];          // K tile | V tile (Q staged across both)
    __half* Ks = KV;
    __half* Vs = KV + 64 * QSTR;

    const int bh = blockIdx.x;                 // 0..31
    const int b  = bh >> 4;
    const int h  = bh & 15;
    const int qbase = blockIdx.y * 128;

    const int tid    = threadIdx.x;
    const int w      = tid >> 5;               // 0..7
    const int lane   = tid & 31;
    const int g      = lane >> 2;
    const int tig    = lane & 3;
    const int lane15 = lane & 15;
    const int lhalf  = lane >> 4;

    // ---- stage Q (128 rows) through KV, extract per-warp A-fragments ----
    const uint4* Qg = reinterpret_cast<const uint4*>(
        q + ((size_t)bh * NSEQ + qbase) * DHEAD);
    #pragma unroll
    for (int i = 0; i < 4; i++) {
        int idx = tid + i * 256;               // 0..1023 chunks of 8 halfs
        int r = idx >> 3, c = idx & 7;
        *reinterpret_cast<uint4*>(KV + r * QSTR + c * 8) = Qg[r * 8 + c];
    }
    __syncthreads();

    uint32_t qa[4][4];
    #pragma unroll
    for (int ks = 0; ks < 4; ks++)
        ldsm_x4(qa[ks][0], qa[ks][1], qa[ks][2], qa[ks][3],
                KV + (w * 16 + lane15) * QSTR + ks * 16 + lhalf * 8);

    float oacc[8][4];
    #pragma unroll
    for (int nt = 0; nt < 8; nt++)
        #pragma unroll
        for (int r = 0; r < 4; r++) oacc[nt][r] = 0.f;
    float m0 = -1e30f, m1 = -1e30f, l0 = 0.f, l1 = 0.f;

    const uint4* Kg = reinterpret_cast<const uint4*>(k + (size_t)bh * NSEQ * DHEAD);
    const uint4* Vg = reinterpret_cast<const uint4*>(v + (size_t)bh * NSEQ * DHEAD);

    for (int kt = 0; kt < NSEQ / 64; kt++) {
        __syncthreads();   // all warps done with previous tile (and Q frags, iter 0)
        #pragma unroll
        for (int i = 0; i < 2; i++) {
            int idx = tid + i * 256;           // 0..511 chunks per tensor
            int r = idx >> 3, c = idx & 7;
            *reinterpret_cast<uint4*>(Ks + r * QSTR + c * 8) = Kg[(kt * 64 + r) * 8 + c];
            *reinterpret_cast<uint4*>(Vs + r * QSTR + c * 8) = Vg[(kt * 64 + r) * 8 + c];
        }
        __syncthreads();

        // ---- S = Q K^T : 16(q) x 64(keys) per warp ----
        float sacc[8][4];
        #pragma unroll
        for (int nt = 0; nt < 8; nt++)
            #pragma unroll
            for (int r = 0; r < 4; r++) sacc[nt][r] = 0.f;

        #pragma unroll
        for (int ks = 0; ks < 4; ks++) {
            uint32_t kb[8][2];
            #pragma unroll
            for (int ntp = 0; ntp < 4; ntp++) {
                int row = ntp * 16 + ((lane & 16) >> 1) + (lane & 7);
                int kof = ks * 16 + (lane & 8);
                ldsm_x4(kb[2 * ntp][0], kb[2 * ntp][1], kb[2 * ntp + 1][0], kb[2 * ntp + 1][1],
                        Ks + row * QSTR + kof);
            }
            #pragma unroll
            for (int nt = 0; nt < 8; nt++)
                mma_f16(sacc[nt], qa[ks][0], qa[ks][1], qa[ks][2], qa[ks][3],
                        kb[nt][0], kb[nt][1]);
        }

        // ---- online off-by-one softmax (scale 1/8 in exp args) ----
        float tm0 = -1e30f, tm1 = -1e30f;
        #pragma unroll
        for (int nt = 0; nt < 8; nt++) {
            tm0 = fmaxf(tm0, fmaxf(sacc[nt][0], sacc[nt][1]));
            tm1 = fmaxf(tm1, fmaxf(sacc[nt][2], sacc[nt][3]));
        }
        tm0 = fmaxf(tm0, __shfl_xor_sync(0xffffffffu, tm0, 1));
        tm0 = fmaxf(tm0, __shfl_xor_sync(0xffffffffu, tm0, 2));
        tm1 = fmaxf(tm1, __shfl_xor_sync(0xffffffffu, tm1, 1));
        tm1 = fmaxf(tm1, __shfl_xor_sync(0xffffffffu, tm1, 2));

        float nm0 = fmaxf(m0, tm0), nm1 = fmaxf(m1, tm1);
        float f0 = __expf((m0 - nm0) * 0.125f), f1 = __expf((m1 - nm1) * 0.125f);
        m0 = nm0; m1 = nm1;

        uint32_t pch[8][2];
        float ps0 = 0.f, ps1 = 0.f;
        #pragma unroll
        for (int nt = 0; nt < 8; nt++) {
            float p0 = __expf((sacc[nt][0] - m0) * 0.125f);
            float p1 = __expf((sacc[nt][1] - m0) * 0.125f);
            float p2 = __expf((sacc[nt][2] - m1) * 0.125f);
            float p3 = __expf((sacc[nt][3] - m1) * 0.125f);
            ps0 += p0 + p1; ps1 += p2 + p3;
            pch[nt][0] = pack_h2(p0, p1);
            pch[nt][1] = pack_h2(p2, p3);
        }
        ps0 += __shfl_xor_sync(0xffffffffu, ps0, 1);
        ps0 += __shfl_xor_sync(0xffffffffu, ps0, 2);
        ps1 += __shfl_xor_sync(0xffffffffu, ps1, 1);
        ps1 += __shfl_xor_sync(0xffffffffu, ps1, 2);
        l0 = l0 * f0 + ps0;
        l1 = l1 * f1 + ps1;

        #pragma unroll
        for (int nt = 0; nt < 8; nt++) {
            oacc[nt][0] *= f0; oacc[nt][1] *= f0;
            oacc[nt][2] *= f1; oacc[nt][3] *= f1;
        }

        // ---- O += P V : S C-frags ARE PV A-frags (half2-packed) ----
        #pragma unroll
        for (int kb2 = 0; kb2 < 4; kb2++) {
            uint32_t pa0 = pch[2 * kb2][0];
            uint32_t pa1 = pch[2 * kb2][1];
            uint32_t pa2 = pch[2 * kb2 + 1][0];
            uint32_t pa3 = pch[2 * kb2 + 1][1];
            uint32_t vb[8][2];
            #pragma unroll
            for (int ntp = 0; ntp < 4; ntp++)
                ldsm_x4_t(vb[2 * ntp][0], vb[2 * ntp][1], vb[2 * ntp + 1][0], vb[2 * ntp + 1][1],
                          Vs + (kb2 * 16 + lane15) * QSTR + ntp * 16 + lhalf * 8);
            #pragma unroll
            for (int nt = 0; nt < 8; nt++)
                mma_f16(oacc[nt], pa0, pa1, pa2, pa3, vb[nt][0], vb[nt][1]);
        }
    }

    // ---- write O (fp16) with 1/(1+l) and slim ----
    float sl = slim[h];
    float inv0 = sl / (1.0f + l0);
    float inv1 = sl / (1.0f + l1);
    int q0 = qbase + w * 16 + g;
    __half* ob0 = out + ((size_t)(b * NSEQ + q0))     * FDIM + h * DHEAD;
    __half* ob1 = out + ((size_t)(b * NSEQ + q0 + 8)) * FDIM + h * DHEAD;
    #pragma unroll
    for (int nt = 0; nt < 8; nt++) {
        int d = nt * 8 + tig * 2;
        *reinterpret_cast<__half2*>(ob0 + d) =
            __floats2half2_rn(oacc[nt][0] * inv0, oacc[nt][1] * inv0);
        *reinterpret_cast<__half2*>(ob1 + d) =
            __floats2half2_rn(oacc[nt][2] * inv1, oacc[nt][3] * inv1);
    }
}

// ---------------------------------------------------------------------------
// Launch
// ---------------------------------------------------------------------------
extern "C" void kernel_launch(void* const* d_in, const int* in_sizes, int n_in,
                              void* d_out, int out_size)
{
    const float* x    = (const float*)d_in[0];
    const float* ln1g = (const float*)d_in[1];
    const float* ln1b = (const float*)d_in[2];
    const float* Wq   = (const float*)d_in[3];
    const float* bq   = (const float*)d_in[4];
    const float* Wk   = (const float*)d_in[5];
    const float* bk   = (const float*)d_in[6];
    const float* Wv   = (const float*)d_in[7];
    const float* bv   = (const float*)d_in[8];
    const float* Wo   = (const float*)d_in[9];
    const float* bo   = (const float*)d_in[10];
    const float* slim = (const float*)d_in[11];
    const float* ln2g = (const float*)d_in[12];
    const float* ln2b = (const float*)d_in[13];
    const float* W1   = (const float*)d_in[14];
    const float* b1   = (const float*)d_in[15];
    const float* W2   = (const float*)d_in[16];
    const float* b2   = (const float*)d_in[17];
    float* out = (float*)d_out;

    float* pout;
    __half *phh, *pqh, *pkh, *pvh, *pah, *ph2, *pm1;
    __half *pwq, *pwk, *pwv, *pwo, *pw1, *pw2;
    cudaGetSymbolAddress((void**)&pout, g_out);
    cudaGetSymbolAddress((void**)&phh,  g_hh);
    cudaGetSymbolAddress((void**)&pqh,  g_qh);
    cudaGetSymbolAddress((void**)&pkh,  g_kh);
    cudaGetSymbolAddress((void**)&pvh,  g_vh);
    cudaGetSymbolAddress((void**)&pah,  g_attnh);
    cudaGetSymbolAddress((void**)&ph2,  g_h2h);
    cudaGetSymbolAddress((void**)&pm1,  g_m1h);
    cudaGetSymbolAddress((void**)&pwq,  g_wq);
    cudaGetSymbolAddress((void**)&pwk,  g_wk);
    cudaGetSymbolAddress((void**)&pwv,  g_wv);
    cudaGetSymbolAddress((void**)&pwo,  g_wo);
    cudaGetSymbolAddress((void**)&pw1,  g_w1);
    cudaGetSymbolAddress((void**)&pw2,  g_w2);

    cudaFuncSetAttribute(qkv_gemm, cudaFuncAttributeMaxDynamicSharedMemorySize, GEMM_SMEM);
    cudaFuncSetAttribute(hgemm<false, true, false, false>,
                         cudaFuncAttributeMaxDynamicSharedMemorySize, GEMM_SMEM);
    cudaFuncSetAttribute(hgemm<true, false, false, true>,
                         cudaFuncAttributeMaxDynamicSharedMemorySize, GEMM_SMEM);
    cudaFuncSetAttribute(hgemm<true, true, false, false>,
                         cudaFuncAttributeMaxDynamicSharedMemorySize, GEMM_SMEM);

    // 0. fused weight conversion (one launch, 8 elem/thread)
    f2h6_kernel<<<dim3(FDIM * MLPD / 2048, 6), 256>>>(
        Wq, Wk, Wv, Wo, W1, W2, pwq, pwk, pwv, pwo, pw1, pw2);

    dim3 gF(FDIM / 128, TOK / 128);
    dim3 gQ(FDIM / 128, TOK / 128, 3);
    dim3 gM(MLPD / 128, TOK / 128);

    // 1. LN1 -> fp16
    ln_kernel<<<TOK, 256>>>(x, ln1g, ln1b, phh);

    // 2. fused QKV projections -> fp16 [b,h,n,d]
    qkv_gemm<<<gQ, 256, GEMM_SMEM>>>(phh, pwq, pwk, pwv, bq, bk, bv, pqh, pkh, pvh);

    // 3. fp16 flash attention (128 q-rows/block)
    attn_h<<<dim3(2 * NHEAD, NSEQ / 128), 256>>>(pqh, pkh, pvh, slim, pah);

    // 4. output projection + residual 1 -> fp32
    hgemm<false, true, false, false><<<gF, 256, GEMM_SMEM>>>(pah, pwo, bo, x, pout, FDIM, FDIM);

    // 5. LN2 -> fp16
    ln_kernel<<<TOK, 256>>>(pout, ln2g, ln2b, ph2);

    // 6. MLP up + GELU -> fp16
    hgemm<true, false, false, true><<<gM, 256, GEMM_SMEM>>>(ph2, pw1, b1, nullptr, pm1, MLPD, FDIM);

    // 7. MLP down + GELU + residual 2 -> fp32 final
    hgemm<true, true, false, false><<<gF, 256, GEMM_SMEM>>>(pm1, pw2, b2, pout, out, FDIM, MLPD);
}